// round 5
// baseline (speedup 1.0000x reference)
#include <cuda_runtime.h>
#include <cuda_fp16.h>
#include <cstdint>

#define M_TOTAL 2048
#define K_TOTAL 4096
#define N_TOTAL 11008
#define GROUPSZ 128
#define NPACK   (N_TOTAL / 8)   // 1376

// Scratch (__device__ globals: allocation-free rules)
__device__ __half g_W[(size_t)K_TOTAL * N_TOTAL];   // ~90 MB fp16 dequantized W [K][N]
__device__ __half g_X[(size_t)M_TOTAL * K_TOTAL];   // ~16 MB fp16 activations [M][K]

// ---------------------------------------------------------------------------
// Kernel 1: dequantize packed int4 -> fp16 [K][N].  (measured 27.7us)
// ---------------------------------------------------------------------------
__global__ void dequant_kernel(const int* __restrict__ qweight,
                               const int* __restrict__ qzeros,
                               const float* __restrict__ scales) {
    int idx = blockIdx.x * blockDim.x + threadIdx.x;
    if (idx >= K_TOTAL * NPACK) return;
    int k  = idx / NPACK;
    int np = idx - k * NPACK;
    int g  = k / GROUPSZ;

    uint32_t qw = ((const uint32_t*)qweight)[idx];
    uint32_t qz = ((const uint32_t*)qzeros)[(size_t)g * NPACK + np];
    const float4* s4 = (const float4*)(scales + (size_t)g * N_TOTAL + np * 8);
    float4 s0 = s4[0];
    float4 s1 = s4[1];
    float s[8] = {s0.x, s0.y, s0.z, s0.w, s1.x, s1.y, s1.z, s1.w};

    __half w[8];
#pragma unroll
    for (int j = 0; j < 8; j++) {
        float wv = (float)((qw >> (4 * j)) & 0xF);
        float zv = (float)((qz >> (4 * j)) & 0xF);
        w[j] = __float2half((wv - zv) * s[j]);
    }
    *(uint4*)(&g_W[(size_t)k * N_TOTAL + np * 8]) = *(uint4*)w;
}

// ---------------------------------------------------------------------------
// Kernel 2: convert x fp32 -> fp16
// ---------------------------------------------------------------------------
__global__ void convert_x_kernel(const float* __restrict__ x) {
    int idx = blockIdx.x * blockDim.x + threadIdx.x;
    if (idx >= M_TOTAL * K_TOTAL / 8) return;
    const float4* xv = (const float4*)x;
    float4 f0 = xv[idx * 2 + 0];
    float4 f1 = xv[idx * 2 + 1];
    __half2 h[4];
    h[0] = __floats2half2_rn(f0.x, f0.y);
    h[1] = __floats2half2_rn(f0.z, f0.w);
    h[2] = __floats2half2_rn(f1.x, f1.y);
    h[3] = __floats2half2_rn(f1.z, f1.w);
    *(uint4*)(&g_X[(size_t)idx * 8]) = *(uint4*)h;
}

// ---------------------------------------------------------------------------
// Kernel 3: GEMM  out[M,N] = X[M,K] * W[K,N] + bias
// mma.sync m16n8k16 fp16->fp32.  BM=128 BN=256 BK=64, 8 warps (2Mx4N),
// warp tile 64x64.  Per k16: 4 A-ldsm.x4 + 4 B-ldsm.x4.trans -> 32 HMMA.
// cp.async double-buffered dynamic smem, padded rows (conflict-free ldsm).
// ---------------------------------------------------------------------------
#define BM 128
#define BN 256
#define BK 64
#define LDA_S 72            // halves per A row  (144B: 8-row ldsm hits distinct banks)
#define LDB_S 264           // halves per B row  (528B)
#define A_SM_BYTES (BM * LDA_S * 2)          // 18432
#define B_SM_BYTES (BK * LDB_S * 2)          // 33792
#define STAGE_BYTES (A_SM_BYTES + B_SM_BYTES)  // 52224
#define SMEM_TOTAL (2 * STAGE_BYTES)           // 104448
#define KT (K_TOTAL / BK)   // 64

__device__ __forceinline__ uint32_t smem_u32(const void* p) {
    return (uint32_t)__cvta_generic_to_shared(p);
}
__device__ __forceinline__ void cp_async_16(uint32_t saddr, const void* gaddr) {
    asm volatile("cp.async.cg.shared.global [%0], [%1], 16;\n" :: "r"(saddr), "l"(gaddr));
}

__global__ void __launch_bounds__(256, 1) gemm_kernel(const float* __restrict__ bias,
                                                      float* __restrict__ out) {
    extern __shared__ char smem[];
    __half* As[2];
    __half* Bs[2];
    As[0] = (__half*)smem;
    Bs[0] = (__half*)(smem + A_SM_BYTES);
    As[1] = (__half*)(smem + STAGE_BYTES);
    Bs[1] = (__half*)(smem + STAGE_BYTES + A_SM_BYTES);

    const int tid  = threadIdx.x;
    const int lane = tid & 31;
    const int warp = tid >> 5;
    const int warp_m = warp & 1;   // 0..1 -> 64 rows
    const int warp_n = warp >> 1;  // 0..3 -> 64 cols
    const int bn = blockIdx.x;     // N tile (43)
    const int bm = blockIdx.y;     // M tile (16)

    // global->smem mapping
    const int a_row = tid >> 1;          // 0..127
    const int a_c0  = (tid & 1) * 8;     // + i*16, i<4
    const int b_row = tid >> 2;          // 0..63
    const int b_c0  = (tid & 3) * 8;     // + i*32, i<8

    const __half* gA = g_X + (size_t)(bm * BM) * K_TOTAL;
    const __half* gB = g_W + (size_t)(bn * BN);

    float acc[4][8][4];
#pragma unroll
    for (int i = 0; i < 4; i++)
#pragma unroll
        for (int j = 0; j < 8; j++)
#pragma unroll
            for (int c = 0; c < 4; c++) acc[i][j][c] = 0.f;

#define LOAD_STAGE(st, kq) do {                                                 \
        const int _k0 = (kq) * BK;                                              \
        _Pragma("unroll")                                                       \
        for (int _i = 0; _i < 4; _i++) {                                        \
            int _c = a_c0 + _i * 16;                                            \
            cp_async_16(smem_u32(&As[st][a_row * LDA_S + _c]),                  \
                        gA + (size_t)a_row * K_TOTAL + _k0 + _c);               \
        }                                                                       \
        _Pragma("unroll")                                                       \
        for (int _i = 0; _i < 8; _i++) {                                        \
            int _c = b_c0 + _i * 32;                                            \
            cp_async_16(smem_u32(&Bs[st][b_row * LDB_S + _c]),                  \
                        gB + (size_t)(_k0 + b_row) * N_TOTAL + _c);             \
        }                                                                       \
        asm volatile("cp.async.commit_group;\n" ::);                            \
    } while (0)

    LOAD_STAGE(0, 0);

    int buf = 0;
    for (int kt = 0; kt < KT; kt++) {
        if (kt + 1 < KT) {
            LOAD_STAGE(buf ^ 1, kt + 1);
            asm volatile("cp.async.wait_group 1;\n" ::);
        } else {
            asm volatile("cp.async.wait_group 0;\n" ::);
        }
        __syncthreads();

        const uint32_t a_base = smem_u32(&As[buf][0]);
        const uint32_t b_base = smem_u32(&Bs[buf][0]);

#pragma unroll
        for (int k16 = 0; k16 < 4; k16++) {
            uint32_t a[4][4];
            uint32_t b[8][2];
#pragma unroll
            for (int mt = 0; mt < 4; mt++) {
                int row = warp_m * 64 + mt * 16 + (lane & 15);
                int col = k16 * 16 + (lane >> 4) * 8;
                uint32_t addr = a_base + (uint32_t)(row * LDA_S + col) * 2u;
                asm volatile("ldmatrix.sync.aligned.m8n8.x4.shared.b16 {%0,%1,%2,%3}, [%4];"
                             : "=r"(a[mt][0]), "=r"(a[mt][1]), "=r"(a[mt][2]), "=r"(a[mt][3])
                             : "r"(addr));
            }
#pragma unroll
            for (int nt = 0; nt < 4; nt++) {
                // 16(k) x 16(n) transposed load -> two n8 B-fragments
                int row = k16 * 16 + (lane & 15);
                int col = warp_n * 64 + nt * 16 + (lane >> 4) * 8;
                uint32_t addr = b_base + (uint32_t)(row * LDB_S + col) * 2u;
                asm volatile("ldmatrix.sync.aligned.m8n8.x4.trans.shared.b16 {%0,%1,%2,%3}, [%4];"
                             : "=r"(b[nt * 2][0]), "=r"(b[nt * 2][1]),
                               "=r"(b[nt * 2 + 1][0]), "=r"(b[nt * 2 + 1][1])
                             : "r"(addr));
            }
#pragma unroll
            for (int mt = 0; mt < 4; mt++) {
#pragma unroll
                for (int nt = 0; nt < 8; nt++) {
                    asm volatile(
                        "mma.sync.aligned.m16n8k16.row.col.f32.f16.f16.f32 "
                        "{%0,%1,%2,%3}, {%4,%5,%6,%7}, {%8,%9}, {%0,%1,%2,%3};"
                        : "+f"(acc[mt][nt][0]), "+f"(acc[mt][nt][1]),
                          "+f"(acc[mt][nt][2]), "+f"(acc[mt][nt][3])
                        : "r"(a[mt][0]), "r"(a[mt][1]), "r"(a[mt][2]), "r"(a[mt][3]),
                          "r"(b[nt][0]), "r"(b[nt][1]));
                }
            }
        }
        __syncthreads();
        buf ^= 1;
    }

    // epilogue: add bias, store fp32
    const int row0 = bm * BM + warp_m * 64 + (lane >> 2);
    const int col0 = bn * BN + warp_n * 64 + (lane & 3) * 2;
#pragma unroll
    for (int mt = 0; mt < 4; mt++) {
#pragma unroll
        for (int nt = 0; nt < 8; nt++) {
            int col = col0 + nt * 8;
            float2 bv = *(const float2*)&bias[col];
            int r0 = row0 + mt * 16;
            float2 v0 = {acc[mt][nt][0] + bv.x, acc[mt][nt][1] + bv.y};
            float2 v1 = {acc[mt][nt][2] + bv.x, acc[mt][nt][3] + bv.y};
            *(float2*)&out[(size_t)r0 * N_TOTAL + col] = v0;
            *(float2*)&out[(size_t)(r0 + 8) * N_TOTAL + col] = v1;
        }
    }
}

// ---------------------------------------------------------------------------
extern "C" void kernel_launch(void* const* d_in, const int* in_sizes, int n_in,
                              void* d_out, int out_size) {
    const float* x       = (const float*)d_in[0];
    const int*   qweight = (const int*)d_in[1];
    const int*   qzeros  = (const int*)d_in[2];
    const float* scales  = (const float*)d_in[3];
    const float* bias    = (const float*)d_in[4];
    float*       out     = (float*)d_out;

    cudaFuncSetAttribute(gemm_kernel,
                         cudaFuncAttributeMaxDynamicSharedMemorySize, SMEM_TOTAL);

    dequant_kernel<<<(K_TOTAL * NPACK + 255) / 256, 256>>>(qweight, qzeros, scales);
    convert_x_kernel<<<(M_TOTAL * K_TOTAL / 8 + 255) / 256, 256>>>(x);
    gemm_kernel<<<dim3(N_TOTAL / BN, M_TOTAL / BM), 256, SMEM_TOTAL>>>(bias, out);
}

// round 7
// speedup vs baseline: 1.0364x; 1.0364x over previous
#include <cuda_runtime.h>
#include <cuda_fp16.h>
#include <cstdint>

#define M_TOTAL 2048
#define K_TOTAL 4096
#define N_TOTAL 11008
#define GROUPSZ 128
#define NPACK   (N_TOTAL / 8)   // 1376

// Scratch (__device__ globals: allocation-free rules)
__device__ __half g_W[(size_t)K_TOTAL * N_TOTAL];   // ~90 MB fp16 dequantized W [K][N]
__device__ __half g_X[(size_t)M_TOTAL * K_TOTAL];   // ~16 MB fp16 activations [M][K]

// ---------------------------------------------------------------------------
// Kernel 1: dequantize packed int4 -> fp16 [K][N].  (measured 27.7us)
// ---------------------------------------------------------------------------
__global__ void dequant_kernel(const int* __restrict__ qweight,
                               const int* __restrict__ qzeros,
                               const float* __restrict__ scales) {
    int idx = blockIdx.x * blockDim.x + threadIdx.x;
    if (idx >= K_TOTAL * NPACK) return;
    int k  = idx / NPACK;
    int np = idx - k * NPACK;
    int g  = k / GROUPSZ;

    uint32_t qw = ((const uint32_t*)qweight)[idx];
    uint32_t qz = ((const uint32_t*)qzeros)[(size_t)g * NPACK + np];
    const float4* s4 = (const float4*)(scales + (size_t)g * N_TOTAL + np * 8);
    float4 s0 = s4[0];
    float4 s1 = s4[1];
    float s[8] = {s0.x, s0.y, s0.z, s0.w, s1.x, s1.y, s1.z, s1.w};

    __half w[8];
#pragma unroll
    for (int j = 0; j < 8; j++) {
        float wv = (float)((qw >> (4 * j)) & 0xF);
        float zv = (float)((qz >> (4 * j)) & 0xF);
        w[j] = __float2half((wv - zv) * s[j]);
    }
    *(uint4*)(&g_W[(size_t)k * N_TOTAL + np * 8]) = *(uint4*)w;
}

// ---------------------------------------------------------------------------
// Kernel 2: convert x fp32 -> fp16
// ---------------------------------------------------------------------------
__global__ void convert_x_kernel(const float* __restrict__ x) {
    int idx = blockIdx.x * blockDim.x + threadIdx.x;
    if (idx >= M_TOTAL * K_TOTAL / 8) return;
    const float4* xv = (const float4*)x;
    float4 f0 = xv[idx * 2 + 0];
    float4 f1 = xv[idx * 2 + 1];
    __half2 h[4];
    h[0] = __floats2half2_rn(f0.x, f0.y);
    h[1] = __floats2half2_rn(f0.z, f0.w);
    h[2] = __floats2half2_rn(f1.x, f1.y);
    h[3] = __floats2half2_rn(f1.z, f1.w);
    *(uint4*)(&g_X[(size_t)idx * 8]) = *(uint4*)h;
}

// ---------------------------------------------------------------------------
// Kernel 3: GEMM  out[M,N] = X[M,K] * W[K,N] + bias
// mma.sync m16n8k16 fp16->fp32.  BM=128 BN=128 BK=64, 8 warps (2Mx4N),
// warp tile 64x32.  3-stage cp.async pipeline, exactly one commit_group per
// iteration (tail iterations reload the current chunk into a dead stage —
// uniform accounting, no empty groups).  2 CTAs/SM.
// ---------------------------------------------------------------------------
#define BM 128
#define BN 128
#define BK 64
#define STAGES 3
#define LDA_S 72            // halves per A row (144B -> conflict-free ldsm)
#define LDB_S 136           // halves per B row (272B -> conflict-free ldsm.trans)
#define A_SM_BYTES (BM * LDA_S * 2)            // 18432
#define B_SM_BYTES (BK * LDB_S * 2)            // 17408
#define STAGE_BYTES (A_SM_BYTES + B_SM_BYTES)  // 35840
#define SMEM_TOTAL (STAGES * STAGE_BYTES)      // 107520
#define KT (K_TOTAL / BK)   // 64

__device__ __forceinline__ uint32_t smem_u32(const void* p) {
    return (uint32_t)__cvta_generic_to_shared(p);
}
__device__ __forceinline__ void cp_async_16(uint32_t saddr, const void* gaddr) {
    asm volatile("cp.async.cg.shared.global [%0], [%1], 16;\n" :: "r"(saddr), "l"(gaddr));
}

__global__ void __launch_bounds__(256) gemm_kernel(const float* __restrict__ bias,
                                                   float* __restrict__ out) {
    extern __shared__ char smem[];

    const int tid  = threadIdx.x;
    const int lane = tid & 31;
    const int warp = tid >> 5;
    const int warp_m = warp & 1;   // 0..1 -> 64 rows
    const int warp_n = warp >> 1;  // 0..3 -> 32 cols
    const int bn = blockIdx.x;     // N tile (86)
    const int bm = blockIdx.y;     // M tile (16)

    // global->smem mapping (8 cp.async per thread per stage)
    const int a_row = tid >> 1;          // 0..127
    const int a_c0  = (tid & 1) * 8;     // + i*16, i<4
    const int b_row = tid >> 2;          // 0..63
    const int b_c0  = (tid & 3) * 8;     // + i*32, i<4

    const __half* gA = g_X + (size_t)(bm * BM) * K_TOTAL;
    const __half* gB = g_W + (size_t)(bn * BN);

    float acc[4][4][4];
#pragma unroll
    for (int i = 0; i < 4; i++)
#pragma unroll
        for (int j = 0; j < 4; j++)
#pragma unroll
            for (int c = 0; c < 4; c++) acc[i][j][c] = 0.f;

#define LOAD_STAGE(st, kq) do {                                                 \
        const int _k0 = (kq) * BK;                                              \
        __half* _As = (__half*)(smem + (st) * STAGE_BYTES);                     \
        __half* _Bs = (__half*)(smem + (st) * STAGE_BYTES + A_SM_BYTES);        \
        _Pragma("unroll")                                                       \
        for (int _i = 0; _i < 4; _i++) {                                        \
            int _c = a_c0 + _i * 16;                                            \
            cp_async_16(smem_u32(&_As[a_row * LDA_S + _c]),                     \
                        gA + (size_t)a_row * K_TOTAL + _k0 + _c);               \
        }                                                                       \
        _Pragma("unroll")                                                       \
        for (int _i = 0; _i < 4; _i++) {                                        \
            int _c = b_c0 + _i * 32;                                            \
            cp_async_16(smem_u32(&_Bs[b_row * LDB_S + _c]),                     \
                        gB + (size_t)(_k0 + b_row) * N_TOTAL + _c);             \
        }                                                                       \
        asm volatile("cp.async.commit_group;\n" ::);                            \
    } while (0)

    // prologue: stages 0 and 1 in flight
    LOAD_STAGE(0, 0);
    LOAD_STAGE(1, 1);

    int sc = 0;   // compute stage index
    int sl = 2;   // next load stage index
    for (int kt = 0; kt < KT; kt++) {
        // need stage kt ready: all groups except the newest one complete
        asm volatile("cp.async.wait_group 1;\n" ::);
        __syncthreads();   // all warps done with stage kt-1 (= stage sl)

        // exactly one commit per iteration; tail reloads current chunk into a
        // stage that is never consumed (harmless, keeps accounting uniform)
        {
            const int knext = (kt + 2 < KT) ? (kt + 2) : kt;
            LOAD_STAGE(sl, knext);
        }

        const uint32_t a_base = smem_u32(smem + sc * STAGE_BYTES);
        const uint32_t b_base = smem_u32(smem + sc * STAGE_BYTES + A_SM_BYTES);

#pragma unroll
        for (int k16 = 0; k16 < 4; k16++) {
            uint32_t a[4][4];
            uint32_t b[4][2];
#pragma unroll
            for (int mt = 0; mt < 4; mt++) {
                int row = warp_m * 64 + mt * 16 + (lane & 15);
                int col = k16 * 16 + (lane >> 4) * 8;
                uint32_t addr = a_base + (uint32_t)(row * LDA_S + col) * 2u;
                asm volatile("ldmatrix.sync.aligned.m8n8.x4.shared.b16 {%0,%1,%2,%3}, [%4];"
                             : "=r"(a[mt][0]), "=r"(a[mt][1]), "=r"(a[mt][2]), "=r"(a[mt][3])
                             : "r"(addr));
            }
#pragma unroll
            for (int np = 0; np < 2; np++) {
                // 16(k) x 16(n) transposed -> two n8 fragments
                int row = k16 * 16 + (lane & 15);
                int col = warp_n * 32 + np * 16 + (lane >> 4) * 8;
                uint32_t addr = b_base + (uint32_t)(row * LDB_S + col) * 2u;
                asm volatile("ldmatrix.sync.aligned.m8n8.x4.trans.shared.b16 {%0,%1,%2,%3}, [%4];"
                             : "=r"(b[np * 2][0]), "=r"(b[np * 2][1]),
                               "=r"(b[np * 2 + 1][0]), "=r"(b[np * 2 + 1][1])
                             : "r"(addr));
            }
#pragma unroll
            for (int mt = 0; mt < 4; mt++) {
#pragma unroll
                for (int nt = 0; nt < 4; nt++) {
                    asm volatile(
                        "mma.sync.aligned.m16n8k16.row.col.f32.f16.f16.f32 "
                        "{%0,%1,%2,%3}, {%4,%5,%6,%7}, {%8,%9}, {%0,%1,%2,%3};"
                        : "+f"(acc[mt][nt][0]), "+f"(acc[mt][nt][1]),
                          "+f"(acc[mt][nt][2]), "+f"(acc[mt][nt][3])
                        : "r"(a[mt][0]), "r"(a[mt][1]), "r"(a[mt][2]), "r"(a[mt][3]),
                          "r"(b[nt][0]), "r"(b[nt][1]));
                }
            }
        }
        sc = (sc + 1 == STAGES) ? 0 : sc + 1;
        sl = (sl + 1 == STAGES) ? 0 : sl + 1;
    }

    // drain all outstanding cp.async before exit
    asm volatile("cp.async.wait_group 0;\n" ::);
    __syncthreads();

    // epilogue: add bias, store fp32
    const int row0 = bm * BM + warp_m * 64 + (lane >> 2);
    const int col0 = bn * BN + warp_n * 32 + (lane & 3) * 2;
#pragma unroll
    for (int mt = 0; mt < 4; mt++) {
#pragma unroll
        for (int nt = 0; nt < 4; nt++) {
            int col = col0 + nt * 8;
            float2 bv = *(const float2*)&bias[col];
            int r0 = row0 + mt * 16;
            float2 v0 = {acc[mt][nt][0] + bv.x, acc[mt][nt][1] + bv.y};
            float2 v1 = {acc[mt][nt][2] + bv.x, acc[mt][nt][3] + bv.y};
            *(float2*)&out[(size_t)r0 * N_TOTAL + col] = v0;
            *(float2*)&out[(size_t)(r0 + 8) * N_TOTAL + col] = v1;
        }
    }
}

// ---------------------------------------------------------------------------
extern "C" void kernel_launch(void* const* d_in, const int* in_sizes, int n_in,
                              void* d_out, int out_size) {
    const float* x       = (const float*)d_in[0];
    const int*   qweight = (const int*)d_in[1];
    const int*   qzeros  = (const int*)d_in[2];
    const float* scales  = (const float*)d_in[3];
    const float* bias    = (const float*)d_in[4];
    float*       out     = (float*)d_out;

    cudaFuncSetAttribute(gemm_kernel,
                         cudaFuncAttributeMaxDynamicSharedMemorySize, SMEM_TOTAL);

    dequant_kernel<<<(K_TOTAL * NPACK + 255) / 256, 256>>>(qweight, qzeros, scales);
    convert_x_kernel<<<(M_TOTAL * K_TOTAL / 8 + 255) / 256, 256>>>(x);
    gemm_kernel<<<dim3(N_TOTAL / BN, M_TOTAL / BM), 256, SMEM_TOTAL>>>(bias, out);
}

// round 8
// speedup vs baseline: 1.2856x; 1.2405x over previous
#include <cuda_runtime.h>
#include <cuda_fp16.h>
#include <cstdint>

#define M_TOTAL 2048
#define K_TOTAL 4096
#define N_TOTAL 11008
#define GROUPSZ 128
#define NPACK   (N_TOTAL / 8)   // 1376

// Scratch (__device__ globals: allocation-free rules)
__device__ __half g_W[(size_t)K_TOTAL * N_TOTAL];   // ~90 MB fp16 dequantized W [K][N]
__device__ __half g_X[(size_t)M_TOTAL * K_TOTAL];   // ~16 MB fp16 activations [M][K]

// ---------------------------------------------------------------------------
// Kernel 1: dequantize packed int4 -> fp16 [K][N].  (measured ~27us)
// ---------------------------------------------------------------------------
__global__ void dequant_kernel(const int* __restrict__ qweight,
                               const int* __restrict__ qzeros,
                               const float* __restrict__ scales) {
    int idx = blockIdx.x * blockDim.x + threadIdx.x;
    if (idx >= K_TOTAL * NPACK) return;
    int k  = idx / NPACK;
    int np = idx - k * NPACK;
    int g  = k / GROUPSZ;

    uint32_t qw = ((const uint32_t*)qweight)[idx];
    uint32_t qz = ((const uint32_t*)qzeros)[(size_t)g * NPACK + np];
    const float4* s4 = (const float4*)(scales + (size_t)g * N_TOTAL + np * 8);
    float4 s0 = s4[0];
    float4 s1 = s4[1];
    float s[8] = {s0.x, s0.y, s0.z, s0.w, s1.x, s1.y, s1.z, s1.w};

    __half w[8];
#pragma unroll
    for (int j = 0; j < 8; j++) {
        float wv = (float)((qw >> (4 * j)) & 0xF);
        float zv = (float)((qz >> (4 * j)) & 0xF);
        w[j] = __float2half((wv - zv) * s[j]);
    }
    *(uint4*)(&g_W[(size_t)k * N_TOTAL + np * 8]) = *(uint4*)w;
}

// ---------------------------------------------------------------------------
// Kernel 2: convert x fp32 -> fp16
// ---------------------------------------------------------------------------
__global__ void convert_x_kernel(const float* __restrict__ x) {
    int idx = blockIdx.x * blockDim.x + threadIdx.x;
    if (idx >= M_TOTAL * K_TOTAL / 8) return;
    const float4* xv = (const float4*)x;
    float4 f0 = xv[idx * 2 + 0];
    float4 f1 = xv[idx * 2 + 1];
    __half2 h[4];
    h[0] = __floats2half2_rn(f0.x, f0.y);
    h[1] = __floats2half2_rn(f0.z, f0.w);
    h[2] = __floats2half2_rn(f1.x, f1.y);
    h[3] = __floats2half2_rn(f1.z, f1.w);
    *(uint4*)(&g_X[(size_t)idx * 8]) = *(uint4*)h;
}

// ---------------------------------------------------------------------------
// Kernel 3: GEMM  out[M,N] = X[M,K] * W[K,N] + bias
// mma.sync m16n8k16 fp16->fp32.  BM=128 BN=128 BK=64, 8 warps (2Mx4N),
// warp tile 64x32.  3-stage cp.async, one commit per iteration, FORCED
// occupancy 2 (launch_bounds(256,2)).  Grid swizzled: blockIdx.x = bm
// (fastest) so each wave reuses every B tile ~16x from L2.
// ---------------------------------------------------------------------------
#define BM 128
#define BN 128
#define BK 64
#define STAGES 3
#define LDA_S 72            // halves per A row (144B -> conflict-free ldsm)
#define LDB_S 136           // halves per B row (272B -> conflict-free ldsm.trans)
#define A_SM_BYTES (BM * LDA_S * 2)            // 18432
#define B_SM_BYTES (BK * LDB_S * 2)            // 17408
#define STAGE_BYTES (A_SM_BYTES + B_SM_BYTES)  // 35840
#define SMEM_TOTAL (STAGES * STAGE_BYTES)      // 107520 (x2 CTA = 215KB <= 228KB)
#define KT (K_TOTAL / BK)   // 64

__device__ __forceinline__ uint32_t smem_u32(const void* p) {
    return (uint32_t)__cvta_generic_to_shared(p);
}
__device__ __forceinline__ void cp_async_16(uint32_t saddr, const void* gaddr) {
    asm volatile("cp.async.cg.shared.global [%0], [%1], 16;\n" :: "r"(saddr), "l"(gaddr));
}

__global__ void __launch_bounds__(256, 2) gemm_kernel(const float* __restrict__ bias,
                                                      float* __restrict__ out) {
    extern __shared__ char smem[];

    const int tid  = threadIdx.x;
    const int lane = tid & 31;
    const int warp = tid >> 5;
    const int warp_m = warp & 1;   // 0..1 -> 64 rows
    const int warp_n = warp >> 1;  // 0..3 -> 32 cols
    const int bm = blockIdx.x;     // M tile (16)  -- fastest: wave spans all bm
    const int bn = blockIdx.y;     // N tile (86)

    // fully-coalesced global->smem mapping: 256B contiguous per half-warp
    const int a_row = tid >> 3;          // 0..31  (+32 per iter, 4 iters)
    const int a_c0  = (tid & 7) * 8;     // 8 thr x 16B = 128B row
    const int b_row = tid >> 4;          // 0..15  (+16 per iter, 4 iters)
    const int b_c0  = (tid & 15) * 8;    // 16 thr x 16B = 256B row

    const __half* gA = g_X + (size_t)(bm * BM) * K_TOTAL;
    const __half* gB = g_W + (size_t)(bn * BN);

    float acc[4][4][4];
#pragma unroll
    for (int i = 0; i < 4; i++)
#pragma unroll
        for (int j = 0; j < 4; j++)
#pragma unroll
            for (int c = 0; c < 4; c++) acc[i][j][c] = 0.f;

#define LOAD_STAGE(st, kq) do {                                                 \
        const int _k0 = (kq) * BK;                                              \
        __half* _As = (__half*)(smem + (st) * STAGE_BYTES);                     \
        __half* _Bs = (__half*)(smem + (st) * STAGE_BYTES + A_SM_BYTES);        \
        _Pragma("unroll")                                                       \
        for (int _i = 0; _i < 4; _i++) {                                        \
            int _r = a_row + _i * 32;                                           \
            cp_async_16(smem_u32(&_As[_r * LDA_S + a_c0]),                      \
                        gA + (size_t)_r * K_TOTAL + _k0 + a_c0);                \
        }                                                                       \
        _Pragma("unroll")                                                       \
        for (int _i = 0; _i < 4; _i++) {                                        \
            int _r = b_row + _i * 16;                                           \
            cp_async_16(smem_u32(&_Bs[_r * LDB_S + b_c0]),                      \
                        gB + (size_t)(_k0 + _r) * N_TOTAL + b_c0);              \
        }                                                                       \
        asm volatile("cp.async.commit_group;\n" ::);                            \
    } while (0)

    // prologue: stages 0 and 1 in flight
    LOAD_STAGE(0, 0);
    LOAD_STAGE(1, 1);

    int sc = 0;   // compute stage
    int sl = 2;   // next load stage
    for (int kt = 0; kt < KT; kt++) {
        asm volatile("cp.async.wait_group 1;\n" ::);
        __syncthreads();   // all warps done with previous compute stage (= sl)

        // exactly one commit per iteration; tail reloads current chunk into a
        // dead stage (never consumed) to keep group accounting uniform
        {
            const int knext = (kt + 2 < KT) ? (kt + 2) : kt;
            LOAD_STAGE(sl, knext);
        }

        const uint32_t a_base = smem_u32(smem + sc * STAGE_BYTES);
        const uint32_t b_base = smem_u32(smem + sc * STAGE_BYTES + A_SM_BYTES);

#pragma unroll
        for (int k16 = 0; k16 < 4; k16++) {
            uint32_t a[4][4];
            uint32_t b[4][2];
#pragma unroll
            for (int mt = 0; mt < 4; mt++) {
                int row = warp_m * 64 + mt * 16 + (lane & 15);
                int col = k16 * 16 + (lane >> 4) * 8;
                uint32_t addr = a_base + (uint32_t)(row * LDA_S + col) * 2u;
                asm volatile("ldmatrix.sync.aligned.m8n8.x4.shared.b16 {%0,%1,%2,%3}, [%4];"
                             : "=r"(a[mt][0]), "=r"(a[mt][1]), "=r"(a[mt][2]), "=r"(a[mt][3])
                             : "r"(addr));
            }
#pragma unroll
            for (int np = 0; np < 2; np++) {
                int row = k16 * 16 + (lane & 15);
                int col = warp_n * 32 + np * 16 + (lane >> 4) * 8;
                uint32_t addr = b_base + (uint32_t)(row * LDB_S + col) * 2u;
                asm volatile("ldmatrix.sync.aligned.m8n8.x4.trans.shared.b16 {%0,%1,%2,%3}, [%4];"
                             : "=r"(b[np * 2][0]), "=r"(b[np * 2][1]),
                               "=r"(b[np * 2 + 1][0]), "=r"(b[np * 2 + 1][1])
                             : "r"(addr));
            }
#pragma unroll
            for (int mt = 0; mt < 4; mt++) {
#pragma unroll
                for (int nt = 0; nt < 4; nt++) {
                    asm volatile(
                        "mma.sync.aligned.m16n8k16.row.col.f32.f16.f16.f32 "
                        "{%0,%1,%2,%3}, {%4,%5,%6,%7}, {%8,%9}, {%0,%1,%2,%3};"
                        : "+f"(acc[mt][nt][0]), "+f"(acc[mt][nt][1]),
                          "+f"(acc[mt][nt][2]), "+f"(acc[mt][nt][3])
                        : "r"(a[mt][0]), "r"(a[mt][1]), "r"(a[mt][2]), "r"(a[mt][3]),
                          "r"(b[nt][0]), "r"(b[nt][1]));
                }
            }
        }
        sc = (sc + 1 == STAGES) ? 0 : sc + 1;
        sl = (sl + 1 == STAGES) ? 0 : sl + 1;
    }

    // drain outstanding cp.async before smem goes dead
    asm volatile("cp.async.wait_group 0;\n" ::);
    __syncthreads();

    // epilogue: add bias, store fp32
    const int row0 = bm * BM + warp_m * 64 + (lane >> 2);
    const int col0 = bn * BN + warp_n * 32 + (lane & 3) * 2;
#pragma unroll
    for (int mt = 0; mt < 4; mt++) {
#pragma unroll
        for (int nt = 0; nt < 4; nt++) {
            int col = col0 + nt * 8;
            float2 bv = *(const float2*)&bias[col];
            int r0 = row0 + mt * 16;
            float2 v0 = {acc[mt][nt][0] + bv.x, acc[mt][nt][1] + bv.y};
            float2 v1 = {acc[mt][nt][2] + bv.x, acc[mt][nt][3] + bv.y};
            *(float2*)&out[(size_t)r0 * N_TOTAL + col] = v0;
            *(float2*)&out[(size_t)(r0 + 8) * N_TOTAL + col] = v1;
        }
    }
}

// ---------------------------------------------------------------------------
extern "C" void kernel_launch(void* const* d_in, const int* in_sizes, int n_in,
                              void* d_out, int out_size) {
    const float* x       = (const float*)d_in[0];
    const int*   qweight = (const int*)d_in[1];
    const int*   qzeros  = (const int*)d_in[2];
    const float* scales  = (const float*)d_in[3];
    const float* bias    = (const float*)d_in[4];
    float*       out     = (float*)d_out;

    cudaFuncSetAttribute(gemm_kernel,
                         cudaFuncAttributeMaxDynamicSharedMemorySize, SMEM_TOTAL);

    dequant_kernel<<<(K_TOTAL * NPACK + 255) / 256, 256>>>(qweight, qzeros, scales);
    convert_x_kernel<<<(M_TOTAL * K_TOTAL / 8 + 255) / 256, 256>>>(x);
    gemm_kernel<<<dim3(M_TOTAL / BM, N_TOTAL / BN), 256, SMEM_TOTAL>>>(bias, out);
}